// round 1
// baseline (speedup 1.0000x reference)
#include <cuda_runtime.h>
#include <cstdint>
#include <cstdio>

// ---------------- problem constants ----------------
#define TPB    128
#define GROUP  16          // batch elements per block
#define NBLK   256         // 256 * 16 = 4096 = B

#define T_IN   96
#define T_OUTC 32
#define TT     128         // decoder length
#define INF    8
#define H1     64
#define K1     72          // 8 (x) + 64 (h) fused K
#define W1S    76          // padded row stride (floats) for W1 in smem
#define H1STR  68          // padded h row stride
#define HD_STR 20          // decoder row stride

// ---------------- smem layout (float offsets) ----------------
#define OFF_W1   0         // 256*76      = 19456
#define OFF_H    19456     // 2*16*68     = 2176
#define OFF_X    21632     // 16*8        = 128
#define OFF_W2   21760     // 4*68        = 272
#define OFF_W2HB 22032     // 8
#define OFF_G2   22040     // 64
#define OFF_H2   22104     // 16
#define OFF_U    22120     // 16
#define OFF_WD1  22136     // 64*20       = 1280
#define OFF_HD   23416     // 2*16*20     = 640
#define OFF_WD2  24056     // 4*20        = 80
#define OFF_G2D  24136     // 64
#define OFF_H2D  24200     // 16
#define OFF_DOUT 24216     // 16*128      = 2048
#define OFF_TMP  26264     // 16*32       = 512
#define SMEM_FLOATS 26776  // 107104 bytes

__device__ __forceinline__ float sigf(float v) {
    return __fdividef(1.0f, 1.0f + __expf(-v));
}
__device__ __forceinline__ float tanhf_fast(float v) {
    // 2*sigmoid(2x)-1 : safe at both extremes, ~1e-7 abs error
    return 2.0f * __fdividef(1.0f, 1.0f + __expf(-2.0f * v)) - 1.0f;
}

__global__ void __launch_bounds__(TPB, 2)
lstm_net_kernel(const float* __restrict__ x,
                const float* __restrict__ e1Wih, const float* __restrict__ e1Whh, const float* __restrict__ e1b,
                const float* __restrict__ e2Wih, const float* __restrict__ e2Whh, const float* __restrict__ e2b,
                const float* __restrict__ d1Wih, const float* __restrict__ d1Whh, const float* __restrict__ d1b,
                const float* __restrict__ d2Wih, const float* __restrict__ d2Whh, const float* __restrict__ d2b,
                const float* __restrict__ fc1W, const float* __restrict__ fc1b,
                const float* __restrict__ fc2W, const float* __restrict__ fc2b,
                float* __restrict__ out)
{
    extern __shared__ float sm[];
    const int tid  = threadIdx.x;
    const int w    = tid >> 5;
    const int lane = tid & 31;
    const int e0g  = blockIdx.x * GROUP;

    // ---------------- stage weights into smem ----------------
    for (int idx = tid; idx < 256 * K1; idx += TPB) {
        int r = idx / K1;
        int k = idx - r * K1;
        sm[OFF_W1 + r * W1S + k] = (k < INF) ? e1Wih[r * INF + k]
                                             : e1Whh[r * H1 + (k - INF)];
    }
    for (int idx = tid; idx < 4 * H1; idx += TPB) {
        int g = idx >> 6, k = idx & 63;
        sm[OFF_W2 + g * H1STR + k] = e2Wih[g * H1 + k];
    }
    if (tid < 4) { sm[OFF_W2HB + tid] = e2Whh[tid]; sm[OFF_W2HB + 4 + tid] = e2b[tid]; }
    for (int idx = tid; idx < 64 * 16; idx += TPB) {
        int j = idx >> 4, k = idx & 15;
        sm[OFF_WD1 + j * HD_STR + k] = d1Whh[j * 16 + k];
    }
    if (tid < 64) {
        sm[OFF_WD1 + tid * HD_STR + 16] = d1Wih[tid];
        sm[OFF_WD1 + tid * HD_STR + 17] = d1b[tid];
        int g = tid >> 4, k = tid & 15;
        sm[OFF_WD2 + g * HD_STR + k] = d2Wih[g * 16 + k];
    }
    if (tid < 4) {
        sm[OFF_WD2 + tid * HD_STR + 16] = d2Whh[tid];
        sm[OFF_WD2 + tid * HD_STR + 17] = d2b[tid];
    }
    for (int idx = tid; idx < 2 * GROUP * H1STR; idx += TPB) sm[OFF_H + idx]  = 0.f;
    for (int idx = tid; idx < 2 * GROUP * HD_STR; idx += TPB) sm[OFF_HD + idx] = 0.f;
    if (tid < GROUP) { sm[OFF_H2 + tid] = 0.f; sm[OFF_H2D + tid] = 0.f; }
    __syncthreads();

    // ---------------- per-thread tiling ----------------
    // e1 cells: elements {E0, E0+4, E0+8, E0+12}, units {U0, U0+1}
    const int E0 = lane & 3;
    const int U0 = (w << 4) + ((lane >> 2) << 1);
    int   RB[2][4];      // float4 row bases into W1
    float b1r[2][4];
    #pragma unroll
    for (int ui = 0; ui < 2; ++ui)
        #pragma unroll
        for (int g = 0; g < 4; ++g) {
            int row = (g << 6) + U0 + ui;
            RB[ui][g]  = row * (W1S / 4);
            b1r[ui][g] = e1b[row];
        }
    float c1[2][4];
    #pragma unroll
    for (int ui = 0; ui < 2; ++ui)
        #pragma unroll
        for (int i = 0; i < 4; ++i) c1[ui][i] = 0.f;

    float c2  = 0.f;     // e2 cell state (threads 0..15)
    float c2d = 0.f;     // d2 cell state (threads 0..15)

    // decoder d1 cells: unit UD, elements {ED, ED+8}
    const int UD = (w << 2) + (lane >> 3);
    const int ED = lane & 7;
    float cd0 = 0.f, cd1 = 0.f;

    int p = 0, pd = 0;

    // ---------------- unified time loop ----------------
    for (int t = 0; t < TT; ++t) {
        if (t < T_IN) {
            // stage x[:, t, :] for this block
            {
                int e = tid >> 3, i = tid & 7;
                sm[OFF_X + e * 8 + i] = x[(size_t)(e0g + e) * (T_IN * INF) + t * INF + i];
            }
            __syncthreads();

            // ---- e1 gates: [16 x 256] = [x_t | h] @ W1^T ----
            const float4* __restrict__ W14 = (const float4*)(sm + OFF_W1);
            const float4* __restrict__ x4  = (const float4*)(sm + OFF_X);
            const float4* __restrict__ h4  = (const float4*)(sm + OFF_H) + p * (GROUP * H1STR / 4);

            float acc[2][4][4];
            #pragma unroll
            for (int ui = 0; ui < 2; ++ui)
                #pragma unroll
                for (int g = 0; g < 4; ++g)
                    #pragma unroll
                    for (int i = 0; i < 4; ++i) acc[ui][g][i] = b1r[ui][g];

            #pragma unroll
            for (int kk = 0; kk < 2; ++kk) {           // x part (K = 0..7)
                float4 a[4];
                #pragma unroll
                for (int i = 0; i < 4; ++i) a[i] = x4[(E0 + 4 * i) * 2 + kk];
                #pragma unroll
                for (int ui = 0; ui < 2; ++ui)
                    #pragma unroll
                    for (int g = 0; g < 4; ++g) {
                        float4 wv = W14[RB[ui][g] + kk];
                        #pragma unroll
                        for (int i = 0; i < 4; ++i) {
                            acc[ui][g][i] += a[i].x * wv.x;
                            acc[ui][g][i] += a[i].y * wv.y;
                            acc[ui][g][i] += a[i].z * wv.z;
                            acc[ui][g][i] += a[i].w * wv.w;
                        }
                    }
            }
            #pragma unroll 4
            for (int kk = 0; kk < 16; ++kk) {          // h part (K = 8..71)
                float4 a[4];
                #pragma unroll
                for (int i = 0; i < 4; ++i) a[i] = h4[(E0 + 4 * i) * 17 + kk];
                #pragma unroll
                for (int ui = 0; ui < 2; ++ui)
                    #pragma unroll
                    for (int g = 0; g < 4; ++g) {
                        float4 wv = W14[RB[ui][g] + 2 + kk];
                        #pragma unroll
                        for (int i = 0; i < 4; ++i) {
                            acc[ui][g][i] += a[i].x * wv.x;
                            acc[ui][g][i] += a[i].y * wv.y;
                            acc[ui][g][i] += a[i].z * wv.z;
                            acc[ui][g][i] += a[i].w * wv.w;
                        }
                    }
            }

            // ---- e1 nonlinearity + h write ----
            float* hn = sm + OFF_H + (1 - p) * (GROUP * H1STR);
            #pragma unroll
            for (int ui = 0; ui < 2; ++ui)
                #pragma unroll
                for (int i = 0; i < 4; ++i) {
                    float ig = sigf(acc[ui][0][i]);
                    float fg = sigf(acc[ui][1][i]);
                    float gg = tanhf_fast(acc[ui][2][i]);
                    float og = sigf(acc[ui][3][i]);
                    float c  = fg * c1[ui][i] + ig * gg;
                    c1[ui][i] = c;
                    hn[(E0 + 4 * i) * H1STR + U0 + ui] = og * tanhf_fast(c);
                }
            __syncthreads();

            // ---- e2 gates (hidden=1): threads 0..63 ----
            if (tid < 64) {
                int e = tid >> 2, g = tid & 3;
                float s = sm[OFF_W2HB + 4 + g] + sm[OFF_W2HB + g] * sm[OFF_H2 + e];
                const float4* hr = (const float4*)(sm + OFF_H + (1 - p) * (GROUP * H1STR) + e * H1STR);
                const float4* w2 = (const float4*)(sm + OFF_W2 + g * H1STR);
                #pragma unroll
                for (int k = 0; k < 16; ++k) {
                    float4 a = hr[k], b = w2[k];
                    s += a.x * b.x + a.y * b.y + a.z * b.z + a.w * b.w;
                }
                sm[OFF_G2 + tid] = s;
            }
            __syncthreads();

            // ---- e2 state + relu -> decoder input u ----
            if (tid < GROUP) {
                float ig = sigf(sm[OFF_G2 + tid * 4 + 0]);
                float fg = sigf(sm[OFF_G2 + tid * 4 + 1]);
                float gg = tanhf_fast(sm[OFF_G2 + tid * 4 + 2]);
                float og = sigf(sm[OFF_G2 + tid * 4 + 3]);
                c2 = fg * c2 + ig * gg;
                float h2 = og * tanhf_fast(c2);
                sm[OFF_H2 + tid] = h2;
                sm[OFF_U + tid]  = fmaxf(h2, 0.f);
            }
            p ^= 1;
        } else {
            // decoder tail: u = x[:, T_IN-T_OUT + (t-T_IN), 0]
            if (tid < GROUP)
                sm[OFF_U + tid] =
                    x[(size_t)(e0g + tid) * (T_IN * INF) + (T_IN - T_OUTC + (t - T_IN)) * INF];
        }
        __syncthreads();  // u ready (and hd1 prev-step writes visible)

        // ---- d1 (in=1, hidden=16): all 128 threads ----
        {
            float accd0[4], accd1[4];
            float u0 = sm[OFF_U + ED];
            float u1 = sm[OFF_U + ED + 8];
            #pragma unroll
            for (int g = 0; g < 4; ++g) {
                int row = (g << 4) + UD;
                float wb = sm[OFF_WD1 + row * HD_STR + 17];
                float wi = sm[OFF_WD1 + row * HD_STR + 16];
                accd0[g] = wb + wi * u0;
                accd1[g] = wb + wi * u1;
            }
            const float4* hd4 = (const float4*)(sm + OFF_HD) + pd * (GROUP * HD_STR / 4);
            #pragma unroll
            for (int k = 0; k < 4; ++k) {
                float4 a0 = hd4[ED * 5 + k];
                float4 a1 = hd4[(ED + 8) * 5 + k];
                #pragma unroll
                for (int g = 0; g < 4; ++g) {
                    const float4 wv = *(const float4*)(sm + OFF_WD1 + ((g << 4) + UD) * HD_STR + 4 * k);
                    accd0[g] += a0.x * wv.x + a0.y * wv.y + a0.z * wv.z + a0.w * wv.w;
                    accd1[g] += a1.x * wv.x + a1.y * wv.y + a1.z * wv.z + a1.w * wv.w;
                }
            }
            float* hdn = sm + OFF_HD + (1 - pd) * (GROUP * HD_STR);
            {
                float ig = sigf(accd0[0]), fg = sigf(accd0[1]);
                float gg = tanhf_fast(accd0[2]), og = sigf(accd0[3]);
                cd0 = fg * cd0 + ig * gg;
                hdn[ED * HD_STR + UD] = og * tanhf_fast(cd0);
            }
            {
                float ig = sigf(accd1[0]), fg = sigf(accd1[1]);
                float gg = tanhf_fast(accd1[2]), og = sigf(accd1[3]);
                cd1 = fg * cd1 + ig * gg;
                hdn[(ED + 8) * HD_STR + UD] = og * tanhf_fast(cd1);
            }
        }
        __syncthreads();

        // ---- d2 gates (in=16, hidden=1): threads 0..63 ----
        if (tid < 64) {
            int e = tid >> 2, g = tid & 3;
            float s = sm[OFF_WD2 + g * HD_STR + 17]
                    + sm[OFF_WD2 + g * HD_STR + 16] * sm[OFF_H2D + e];
            const float4* hr = (const float4*)(sm + OFF_HD + (1 - pd) * (GROUP * HD_STR) + e * HD_STR);
            #pragma unroll
            for (int k = 0; k < 4; ++k) {
                float4 a = hr[k];
                const float4 b = *(const float4*)(sm + OFF_WD2 + g * HD_STR + 4 * k);
                s += a.x * b.x + a.y * b.y + a.z * b.z + a.w * b.w;
            }
            sm[OFF_G2D + tid] = s;
        }
        __syncthreads();

        // ---- d2 state -> dout[t] ----
        if (tid < GROUP) {
            float ig = sigf(sm[OFF_G2D + tid * 4 + 0]);
            float fg = sigf(sm[OFF_G2D + tid * 4 + 1]);
            float gg = tanhf_fast(sm[OFF_G2D + tid * 4 + 2]);
            float og = sigf(sm[OFF_G2D + tid * 4 + 3]);
            c2d = fg * c2d + ig * gg;
            float hh = og * tanhf_fast(c2d);
            sm[OFF_H2D + tid]          = hh;
            sm[OFF_DOUT + tid * TT + t] = hh;
        }
        pd ^= 1;
    }
    __syncthreads();

    // ---------------- FC head ----------------
    #pragma unroll
    for (int r = 0; r < 4; ++r) {
        int idx = tid + TPB * r;
        int e = idx >> 5, j = idx & 31;
        float s = fc1b[j];
        const float4* dr = (const float4*)(sm + OFF_DOUT + e * TT);
        const float4* wr = (const float4*)(fc1W + j * TT);
        #pragma unroll 8
        for (int k = 0; k < 32; ++k) {
            float4 a = dr[k], b = wr[k];
            s += a.x * b.x + a.y * b.y + a.z * b.z + a.w * b.w;
        }
        sm[OFF_TMP + e * 32 + j] = s;
    }
    __syncthreads();
    #pragma unroll
    for (int r = 0; r < 4; ++r) {
        int idx = tid + TPB * r;
        int e = idx >> 5, o = idx & 31;
        float s = fc2b[o];
        const float4* tr = (const float4*)(sm + OFF_TMP + e * 32);
        const float4* wr = (const float4*)(fc2W + o * 32);
        #pragma unroll
        for (int k = 0; k < 8; ++k) {
            float4 a = tr[k], b = wr[k];
            s += a.x * b.x + a.y * b.y + a.z * b.z + a.w * b.w;
        }
        out[(size_t)(e0g + e) * T_OUTC + o] = s;
    }
}

extern "C" void kernel_launch(void* const* d_in, const int* in_sizes, int n_in,
                              void* d_out, int out_size) {
    (void)in_sizes; (void)n_in; (void)out_size;
    const float* x      = (const float*)d_in[0];
    const float* e1Wih  = (const float*)d_in[1];
    const float* e1Whh  = (const float*)d_in[2];
    const float* e1b    = (const float*)d_in[3];
    const float* e2Wih  = (const float*)d_in[4];
    const float* e2Whh  = (const float*)d_in[5];
    const float* e2b    = (const float*)d_in[6];
    const float* d1Wih  = (const float*)d_in[7];
    const float* d1Whh  = (const float*)d_in[8];
    const float* d1b    = (const float*)d_in[9];
    const float* d2Wih  = (const float*)d_in[10];
    const float* d2Whh  = (const float*)d_in[11];
    const float* d2b    = (const float*)d_in[12];
    const float* fc1W   = (const float*)d_in[13];
    const float* fc1b   = (const float*)d_in[14];
    const float* fc2W   = (const float*)d_in[15];
    const float* fc2b   = (const float*)d_in[16];

    const size_t smem = SMEM_FLOATS * sizeof(float);  // 107104 B
    cudaFuncSetAttribute(lstm_net_kernel,
                         cudaFuncAttributeMaxDynamicSharedMemorySize, (int)smem);
    lstm_net_kernel<<<NBLK, TPB, smem>>>(x,
        e1Wih, e1Whh, e1b, e2Wih, e2Whh, e2b,
        d1Wih, d1Whh, d1b, d2Wih, d2Whh, d2b,
        fc1W, fc1b, fc2W, fc2b, (float*)d_out);
}